// round 8
// baseline (speedup 1.0000x reference)
#include <cuda_runtime.h>
#include <cuda_bf16.h>
#include <stdint.h>
#include <math.h>

#define Bb 4
#define Ss 128
#define Nn 512
#define Hh 64
#define Mm 2048
#define XSTR 68
#define SSTR 132
#define NTH 1024

// bf16 tiles: stride 72 elements (144 B/row) -> u32/ldmatrix bank map 4g+q, conflict-free
#define XTILE_B 18432u   // 128 x 72 x 2
#define WTILE_B 9216u    // 64 x 72 x 2

// smem byte offsets
#define OFF_XTRF 0u        // fp32 [128][68] residual            34816
#define OFF_VSM  34816u    // fp32 [128][68] V                   34816
#define OFF_XTR3 69632u    // Xtr bf16 x3 -> P bf16 x3 overlay   55296
#define OFF_XTX3 124928u   // Xtx bf16 x3                        55296
#define OFF_G3   180224u   // G bf16 x3                          27648
#define OFF_WV2  207872u   // Wv bf16 x2                         18432
#define OFF_TAIL 226304u   // rb128 cb128 sg64 sb64 sbv64 = 1792
#define OFF_SC   69632u    // scores fp32 [128][132] overlay (67584 <= 110592)
#define SMEM_SZ  228096u

// ---------------- precomputed operands ----------------
__device__ float g_Gt[Hh*Hh];   // [c][h] = scale * sum_o Wq[o][h] Wk[o][c]
__device__ float g_u[Hh];
__device__ float g_w[Hh];
__device__ float g_c0;
__device__ __align__(16) uint32_t g_wpack[11520]; // G 3 terms (64x36 words each) + Wv 2 terms

__global__ void precompute_k(const float* __restrict__ Wq, const float* __restrict__ bq,
                             const float* __restrict__ Wk, const float* __restrict__ bk) {
    int gid = blockIdx.x * blockDim.x + threadIdx.x;
    const float scale = 0.125f;
    if (gid < Hh * Hh) {
        int c = gid >> 6, h = gid & 63;
        float s = 0.f;
        #pragma unroll 8
        for (int o = 0; o < Hh; o++) s += Wq[o*Hh + h] * Wk[o*Hh + c];
        g_Gt[gid] = s * scale;
    }
    if (gid < Hh) {
        float s = 0.f, t = 0.f;
        #pragma unroll 8
        for (int o = 0; o < Hh; o++) { s += Wq[o*Hh + gid] * bk[o]; t += Wk[o*Hh + gid] * bq[o]; }
        g_u[gid] = s; g_w[gid] = t;
        g_u[gid] *= scale; g_w[gid] *= scale;
    }
    if (gid == 0) {
        float s = 0.f;
        for (int o = 0; o < Hh; o++) s += bq[o] * bk[o];
        g_c0 = s * scale;
    }
}

__device__ __forceinline__ void split3b(float x, unsigned short& h, unsigned short& m, unsigned short& l) {
    __nv_bfloat16 bh = __float2bfloat16(x);
    float r1 = x - __bfloat162float(bh);
    __nv_bfloat16 bm = __float2bfloat16(r1);
    float r2 = r1 - __bfloat162float(bm);
    h = __bfloat16_as_ushort(bh);
    m = __bfloat16_as_ushort(bm);
    l = __bfloat16_as_ushort(__float2bfloat16(r2));
}

// g_wpack layout: [G t0|G t1|G t2|Wv t0|Wv t1], each term 64 rows x 36 words
__global__ void precompute_pack(const float* __restrict__ Wv) {
    int gid = blockIdx.x * blockDim.x + threadIdx.x;
    if (gid >= 11520) return;
    int isW = (gid >= 6912);
    int rem = isW ? (gid - 6912) : gid;
    int t = rem / 2304; rem %= 2304;
    int r = rem / 36, w = rem % 36;
    const float* M = isW ? Wv : g_Gt;
    float v0 = (2*w   < 64) ? M[r*64 + 2*w]   : 0.f;
    float v1 = (2*w+1 < 64) ? M[r*64 + 2*w+1] : 0.f;
    unsigned short h0,m0,l0,h1,m1,l1;
    split3b(v0,h0,m0,l0); split3b(v1,h1,m1,l1);
    unsigned short s0, s1;
    if (t == 0)      { s0 = h0; s1 = h1; }
    else if (t == 1) { s0 = m0; s1 = m1; }
    else             { s0 = l0; s1 = l1; }
    g_wpack[gid] = ((uint32_t)s1 << 16) | s0;
}

// ---------------- ptx helpers ----------------
__device__ __forceinline__ uint32_t sm2u(const void* p) {
    uint32_t a;
    asm("{ .reg .u64 t; cvta.to.shared.u64 t, %1; cvt.u32.u64 %0, t; }" : "=r"(a) : "l"(p));
    return a;
}
__device__ __forceinline__ void ldsm4(uint32_t& r0, uint32_t& r1, uint32_t& r2, uint32_t& r3, uint32_t a) {
    asm volatile("ldmatrix.sync.aligned.m8n8.x4.shared.b16 {%0,%1,%2,%3}, [%4];"
                 : "=r"(r0), "=r"(r1), "=r"(r2), "=r"(r3) : "r"(a));
}
__device__ __forceinline__ void mma16(float c[4], uint32_t a0, uint32_t a1, uint32_t a2, uint32_t a3,
                                      uint32_t b0, uint32_t b1) {
    asm volatile(
        "mma.sync.aligned.m16n8k16.row.col.f32.bf16.bf16.f32 "
        "{%0,%1,%2,%3}, {%4,%5,%6,%7}, {%8,%9}, {%0,%1,%2,%3};"
        : "+f"(c[0]), "+f"(c[1]), "+f"(c[2]), "+f"(c[3])
        : "r"(a0), "r"(a1), "r"(a2), "r"(a3), "r"(b0), "r"(b1));
}
__device__ __forceinline__ unsigned f2mono(float v) {
    unsigned u = __float_as_uint(v);
    return (u & 0x80000000u) ? ~u : (u | 0x80000000u);
}
__device__ __forceinline__ float mono2f(unsigned k) {
    unsigned u = (k & 0x80000000u) ? (k ^ 0x80000000u) : ~k;
    return __uint_as_float(u);
}

// One multi-pass bf16 GEMM: warp tile m16 x n32, K=64, operand tiles stride 144 B.
// aAddrBase/bAddr0Base: per-lane ldmatrix addresses (term 0). npass product pairs in ia[],ib[].
template<int NP>
__device__ __forceinline__ void gemm_mp(uint32_t aBase, uint32_t bBase, uint32_t aTile, uint32_t bTile,
                                        const int* ia, const int* ib, float acc[4][4]) {
    #pragma unroll
    for (int p = 0; p < NP; p++) {
        uint32_t pa  = aBase + (uint32_t)ia[p] * aTile;
        uint32_t pb0 = bBase + (uint32_t)ib[p] * bTile;
        uint32_t pb1 = pb0 + 16u * 144u;
        #pragma unroll
        for (int k = 0; k < 4; k++) {
            uint32_t a0,a1,a2,a3, b00,b01,b10,b11, b20,b21,b30,b31;
            ldsm4(a0,a1,a2,a3, pa);
            ldsm4(b00,b01,b10,b11, pb0);
            ldsm4(b20,b21,b30,b31, pb1);
            mma16(acc[0], a0,a1,a2,a3, b00,b01);
            mma16(acc[1], a0,a1,a2,a3, b10,b11);
            mma16(acc[2], a0,a1,a2,a3, b20,b21);
            mma16(acc[3], a0,a1,a2,a3, b30,b31);
            pa += 32; pb0 += 32; pb1 += 32;
        }
    }
}

extern __shared__ char smraw[];
__global__ void __launch_bounds__(NTH, 1)
fused_align_k(const float* __restrict__ traffic, const float* __restrict__ text,
              const float* __restrict__ Wv, const float* __restrict__ bv,
              const float* __restrict__ gamma, const float* __restrict__ beta,
              const int* __restrict__ topk_p,
              float* __restrict__ out_main, float* __restrict__ out_attn) {
    char* sm = smraw;
    float* xt_tr = (float*)(sm + OFF_XTRF);
    float* vsm   = (float*)(sm + OFF_VSM);
    float* sc    = (float*)(sm + OFF_SC);
    float* tailf = (float*)(sm + OFF_TAIL);
    float* rb  = tailf;
    float* cb  = tailf + 128;
    float* sg  = tailf + 256;
    float* sb  = tailf + 320;
    float* sbv = tailf + 384;
    const uint32_t smb = sm2u(sm);

    const int tid = threadIdx.x;
    const int lane = tid & 31;
    const int wrp = tid >> 5;
    const int m = blockIdx.x;
    const int b = m >> 9;
    const int n = m & (Nn - 1);

    const float* tr_base = traffic + ((size_t)b * Ss * Nn + n) * Hh;
    const float* tx_base = text    + ((size_t)b * Ss * Nn + n) * Hh;

    // ---- Stage 0: weights copy + tile loads/splits + fused biases ----
    for (int i = tid; i < 2880; i += NTH)
        ((uint4*)(sm + OFF_G3))[i] = ((const uint4*)g_wpack)[i];
    #pragma unroll
    for (int it = 0; it < 2; it++) {
        int i = tid + it * NTH;
        int r = i >> 4, f = i & 15;
        float4 a  = *(const float4*)(tr_base + (size_t)r * Nn * Hh + f * 4);
        float4 bx = *(const float4*)(tx_base + (size_t)r * Nn * Hh + f * 4);
        *(float4*)(xt_tr + r * XSTR + f * 4) = a;
        unsigned short h[4], md[4], lo[4];
        uint32_t rowb = (uint32_t)r * 144u + (uint32_t)f * 8u;
        // Xtr split
        split3b(a.x,h[0],md[0],lo[0]); split3b(a.y,h[1],md[1],lo[1]);
        split3b(a.z,h[2],md[2],lo[2]); split3b(a.w,h[3],md[3],lo[3]);
        *(uint2*)(sm + OFF_XTR3 + 0*XTILE_B + rowb) = make_uint2(((uint32_t)h[1]<<16)|h[0], ((uint32_t)h[3]<<16)|h[2]);
        *(uint2*)(sm + OFF_XTR3 + 1*XTILE_B + rowb) = make_uint2(((uint32_t)md[1]<<16)|md[0], ((uint32_t)md[3]<<16)|md[2]);
        *(uint2*)(sm + OFF_XTR3 + 2*XTILE_B + rowb) = make_uint2(((uint32_t)lo[1]<<16)|lo[0], ((uint32_t)lo[3]<<16)|lo[2]);
        // Xtx split
        split3b(bx.x,h[0],md[0],lo[0]); split3b(bx.y,h[1],md[1],lo[1]);
        split3b(bx.z,h[2],md[2],lo[2]); split3b(bx.w,h[3],md[3],lo[3]);
        *(uint2*)(sm + OFF_XTX3 + 0*XTILE_B + rowb) = make_uint2(((uint32_t)h[1]<<16)|h[0], ((uint32_t)h[3]<<16)|h[2]);
        *(uint2*)(sm + OFF_XTX3 + 1*XTILE_B + rowb) = make_uint2(((uint32_t)md[1]<<16)|md[0], ((uint32_t)md[3]<<16)|md[2]);
        *(uint2*)(sm + OFF_XTX3 + 2*XTILE_B + rowb) = make_uint2(((uint32_t)lo[1]<<16)|lo[0], ((uint32_t)lo[3]<<16)|lo[2]);
        // fused bias partials (16 lanes per row)
        float4 uu = *(const float4*)(g_u + f * 4);
        float4 ww = *(const float4*)(g_w + f * 4);
        float pr = a.x*uu.x + a.y*uu.y + a.z*uu.z + a.w*uu.w;
        float pc = bx.x*ww.x + bx.y*ww.y + bx.z*ww.z + bx.w*ww.w;
        #pragma unroll
        for (int o = 8; o > 0; o >>= 1) {
            pr += __shfl_xor_sync(0xffffffffu, pr, o);
            pc += __shfl_xor_sync(0xffffffffu, pc, o);
        }
        if (f == 0) { rb[r] = pr + g_c0; cb[r] = pc; }
    }
    if (tid < 64) { sg[tid] = gamma[tid]; sb[tid] = beta[tid]; sbv[tid] = bv[tid]; }
    __syncthreads();

    const int g = lane >> 2, q = lane & 3;
    // ldmatrix per-lane address components
    const uint32_t aRow = (uint32_t)(lane & 15);
    const uint32_t aKof = ((uint32_t)(lane >> 4) & 1u) * 16u;
    const uint32_t bRow = (uint32_t)((lane & 7) + ((lane >= 16) ? 8 : 0));
    const uint32_t bKof = ((uint32_t)(lane >> 3) & 1u) * 16u;

    static const int IA6[6] = {0,0,1,1,0,2};
    static const int IB6[6] = {0,1,0,1,2,0};
    static const int IA4[4] = {0,0,1,1};
    static const int IB4[4] = {0,1,0,1};

    // ---- Phase 1: P (warps 0-15) / V (warps 16-31) ----
    float accPV[4][4];
    #pragma unroll
    for (int i = 0; i < 4; i++)
        #pragma unroll
        for (int j = 0; j < 4; j++) accPV[i][j] = 0.f;
    int w2 = (wrp < 16) ? wrp : (wrp - 16);
    const int mb = (w2 >> 1) * 16, n0 = (w2 & 1) * 32;
    {
        uint32_t aB, bB;
        if (wrp < 16) {
            aB = smb + OFF_XTR3 + (mb + aRow) * 144u + aKof;
            bB = smb + OFF_G3   + (n0 + bRow) * 144u + bKof;
            gemm_mp<6>(aB, bB, XTILE_B, WTILE_B, IA6, IB6, accPV);
        } else {
            aB = smb + OFF_XTX3 + (mb + aRow) * 144u + aKof;
            bB = smb + OFF_WV2  + (n0 + bRow) * 144u + bKof;
            gemm_mp<4>(aB, bB, XTILE_B, WTILE_B, IA4, IB4, accPV);
            // store V (+bv) now: vsm rows are exclusive to this warp's tile
            #pragma unroll
            for (int nt = 0; nt < 4; nt++) {
                int col = n0 + 8*nt + 2*q;
                *(float2*)(vsm + (mb + g) * XSTR + col)     = make_float2(accPV[nt][0] + sbv[col], accPV[nt][1] + sbv[col+1]);
                *(float2*)(vsm + (mb + g + 8) * XSTR + col) = make_float2(accPV[nt][2] + sbv[col], accPV[nt][3] + sbv[col+1]);
            }
        }
    }
    __syncthreads();     // all Xtr3/G reads complete
    if (wrp < 16) {      // split P -> bf16 x3, overlay Xtr3
        #pragma unroll
        for (int nt = 0; nt < 4; nt++) {
            int col = n0 + 8*nt + 2*q;
            unsigned short h0,m0,l0,h1,m1,l1;
            uint32_t r0b = (uint32_t)(mb + g) * 144u + (uint32_t)col * 2u;
            uint32_t r1b = (uint32_t)(mb + g + 8) * 144u + (uint32_t)col * 2u;
            split3b(accPV[nt][0],h0,m0,l0); split3b(accPV[nt][1],h1,m1,l1);
            *(uint32_t*)(sm + OFF_XTR3 + 0*XTILE_B + r0b) = ((uint32_t)h1<<16)|h0;
            *(uint32_t*)(sm + OFF_XTR3 + 1*XTILE_B + r0b) = ((uint32_t)m1<<16)|m0;
            *(uint32_t*)(sm + OFF_XTR3 + 2*XTILE_B + r0b) = ((uint32_t)l1<<16)|l0;
            split3b(accPV[nt][2],h0,m0,l0); split3b(accPV[nt][3],h1,m1,l1);
            *(uint32_t*)(sm + OFF_XTR3 + 0*XTILE_B + r1b) = ((uint32_t)h1<<16)|h0;
            *(uint32_t*)(sm + OFF_XTR3 + 1*XTILE_B + r1b) = ((uint32_t)m1<<16)|m0;
            *(uint32_t*)(sm + OFF_XTR3 + 2*XTILE_B + r1b) = ((uint32_t)l1<<16)|l0;
        }
    }
    __syncthreads();     // P3 visible

    // ---- Phase 2: S = P3 @ Xtx3^T (all 32 warps; m16 x n32) ----
    float accS[4][4];
    #pragma unroll
    for (int i = 0; i < 4; i++)
        #pragma unroll
        for (int j = 0; j < 4; j++) accS[i][j] = 0.f;
    const int smbm = (wrp >> 2) * 16, sn0 = (wrp & 3) * 32;
    {
        uint32_t aB = smb + OFF_XTR3 + (smbm + aRow) * 144u + aKof;
        uint32_t bB = smb + OFF_XTX3 + (sn0 + bRow) * 144u + bKof;
        gemm_mp<6>(aB, bB, XTILE_B, XTILE_B, IA6, IB6, accS);
    }
    __syncthreads();     // all P3/Xtx3 reads complete -> safe to overlay scores
    #pragma unroll
    for (int nt = 0; nt < 4; nt++) {
        int col = sn0 + 8*nt + 2*q;
        *(float2*)(sc + (smbm + g) * SSTR + col)     = make_float2(accS[nt][0], accS[nt][1]);
        *(float2*)(sc + (smbm + g + 8) * SSTR + col) = make_float2(accS[nt][2], accS[nt][3]);
    }
    __syncthreads();

    // ---- Stage 3: per-row top-k + softmax + attn + sparse AV + LN ----
    int kk = 16;
    if (topk_p) { kk = topk_p[0]; if (kk < 1) kk = 1; if (kk > 32) kk = 32; }

    const int r0 = wrp * 4;
    float* attn_base = out_attn + (size_t)m * Ss * Ss;
    const unsigned FULL = 0xffffffffu;

    for (int ri = 0; ri < 4; ++ri) {
        const int s = r0 + ri;
        const float rbias = rb[s];
        float o0 = sc[s * SSTR + lane]      + rbias + cb[lane];
        float o1 = sc[s * SSTR + lane + 32] + rbias + cb[lane + 32];
        float o2 = sc[s * SSTR + lane + 64] + rbias + cb[lane + 64];
        float o3 = sc[s * SSTR + lane + 96] + rbias + cb[lane + 96];
        unsigned k0 = f2mono(o0), k1 = f2mono(o1), k2 = f2mono(o2), k3 = f2mono(o3);
        unsigned l0 = k0, l1 = k1, l2 = k2, l3 = k3;
        unsigned maxk = 0, thrk = 0, selk = 0; int seli = 0;

        for (int it = 0; it < kk; ++it) {
            unsigned lb = l0; int slot = 0;
            if (l1 > lb) { lb = l1; slot = 1; }
            if (l2 > lb) { lb = l2; slot = 2; }
            if (l3 > lb) { lb = l3; slot = 3; }
            unsigned mw = __reduce_max_sync(FULL, lb);
            unsigned cand = (lb == mw) ? (unsigned)(slot * 32 + lane) : 0xffffffffu;
            unsigned tsel = __reduce_min_sync(FULL, cand);
            if (it == 0) maxk = mw;
            thrk = mw;
            if (lane == (int)(tsel & 31)) {
                int js = tsel >> 5;
                if (js == 0) l0 = 0; else if (js == 1) l1 = 0;
                else if (js == 2) l2 = 0; else l3 = 0;
            }
            if (lane == it) { selk = mw; seli = (int)tsel; }
        }

        float maxv = mono2f(maxk);
        float e0 = (k0 >= thrk) ? __expf(o0 - maxv) : 0.f;
        float e1 = (k1 >= thrk) ? __expf(o1 - maxv) : 0.f;
        float e2 = (k2 >= thrk) ? __expf(o2 - maxv) : 0.f;
        float e3 = (k3 >= thrk) ? __expf(o3 - maxv) : 0.f;
        float z = e0 + e1 + e2 + e3;
        #pragma unroll
        for (int off = 16; off > 0; off >>= 1) z += __shfl_xor_sync(FULL, z, off);
        float inv = 1.0f / z;

        float* ab = attn_base + (size_t)s * Ss;
        ab[lane]      = e0 * inv;
        ab[lane + 32] = e1 * inv;
        ab[lane + 64] = e2 * inv;
        ab[lane + 96] = e3 * inv;

        float p = (lane < kk) ? __expf(mono2f(selk) - maxv) * inv : 0.f;
        float a0 = 0.f, a1 = 0.f;
        for (int i2 = 0; i2 < kk; i2++) {
            float pi = __shfl_sync(FULL, p, i2);
            int   ti = __shfl_sync(FULL, seli, i2);
            const float* vr = vsm + ti * XSTR;
            a0 += pi * vr[lane];
            a1 += pi * vr[lane + 32];
        }

        float rr0 = a0 + xt_tr[s * XSTR + lane];
        float rr1 = a1 + xt_tr[s * XSTR + lane + 32];
        float sm1 = rr0 + rr1;
        #pragma unroll
        for (int off = 16; off > 0; off >>= 1) sm1 += __shfl_xor_sync(FULL, sm1, off);
        float mu = sm1 * (1.0f / 64.0f);
        float d0 = rr0 - mu, d1 = rr1 - mu;
        float sq = d0 * d0 + d1 * d1;
        #pragma unroll
        for (int off = 16; off > 0; off >>= 1) sq += __shfl_xor_sync(FULL, sq, off);
        float inv_sd = rsqrtf(sq * (1.0f / 64.0f) + 1e-5f);

        float* ob = out_main + (((size_t)(b * Ss + s)) * Nn + n) * Hh;
        ob[lane]      = d0 * inv_sd * sg[lane]      + sb[lane];
        ob[lane + 32] = d1 * inv_sd * sg[lane + 32] + sb[lane + 32];
    }
}

extern "C" void kernel_launch(void* const* d_in, const int* in_sizes, int n_in,
                              void* d_out, int out_size) {
    const float* traffic = (const float*)d_in[0];
    const float* text    = (const float*)d_in[1];
    const float* Wq      = (const float*)d_in[2];
    const float* bq      = (const float*)d_in[3];
    const float* Wk      = (const float*)d_in[4];
    const float* bk      = (const float*)d_in[5];
    const float* Wv      = (const float*)d_in[6];
    const float* bv      = (const float*)d_in[7];
    const float* gamma   = (const float*)d_in[8];
    const float* beta    = (const float*)d_in[9];
    const int*   topk    = (n_in > 10) ? (const int*)d_in[10] : nullptr;

    float* out  = (float*)d_out;
    float* attn = out + (size_t)Bb * Ss * Nn * Hh;

    cudaFuncSetAttribute(fused_align_k, cudaFuncAttributeMaxDynamicSharedMemorySize, (int)SMEM_SZ);

    precompute_k<<<16, 256>>>(Wq, bq, Wk, bk);
    precompute_pack<<<45, 256>>>(Wv);
    fused_align_k<<<Mm, NTH, SMEM_SZ>>>(traffic, text, Wv, bv, gamma, beta, topk, out, attn);
}

// round 9
// speedup vs baseline: 1.2783x; 1.2783x over previous
#include <cuda_runtime.h>
#include <stdint.h>
#include <math.h>

#define Bb 4
#define Ss 128
#define Nn 512
#define Hh 64
#define Mm 2048
#define XS 68      // fp32 tiles stride
#define WS 72      // tf32 split tiles stride (conflict-free LDS.64: banks 8g+2q)
#define SS 132     // scores stride
#define NTH 1024

// smem float offsets
#define F_XTR  0       // fp32 Xtr [128][68]                         8704
#define F_XTXH 8704    // tf32 hi Xtx [128][72] (k-pair-permuted)    9216
#define F_XTXL 17920   // tf32 lo                                    9216
#define F_W    27136   // Gh|Gl|Wvh|Wvl (4608 each) -> PH|PL (9216)  18432
#define F_VSM  45568   // fp32 V [128][68]                           8704
#define F_TAIL 54272   // rb128 cb128 sg64 sb64 sbv64                448
#define F_SC   8704    // scores [128][132] overlay Xtx (post phase2)
#define F_AVL  27136   // av lists [128][32] float2 overlay W (post phase2)
#define SMEM_FLOATS 54720

// k-pair permutation: pairs (k, k+4) adjacent
__host__ __device__ __forceinline__ int kperm(int k) {
    return (k & ~7) | ((k & 3) << 1) | ((k >> 2) & 1);
}
__host__ __device__ __forceinline__ int kperm_inv(int p) {
    return (p & ~7) | ((p & 1) << 2) | ((p >> 1) & 3);
}

// ---------------- precomputed operands ----------------
__device__ float g_Gt[Hh*Hh];     // [c][h'] = scale * sum_o Wq[o][h'] Wk[o][c]
__device__ float g_u[Hh];
__device__ float g_w[Hh];
__device__ float g_c0;
__device__ __align__(16) float g_wsplit[18432]; // Gh|Gl (unperm) | Wvh|Wvl (k-permuted), [64][72]

__global__ void precompute_k(const float* __restrict__ Wq, const float* __restrict__ bq,
                             const float* __restrict__ Wk, const float* __restrict__ bk) {
    int gid = blockIdx.x * blockDim.x + threadIdx.x;
    const float scale = 0.125f;
    if (gid < Hh * Hh) {
        int c = gid >> 6, h = gid & 63;
        float s = 0.f;
        #pragma unroll 8
        for (int o = 0; o < Hh; o++) s += Wq[o*Hh + h] * Wk[o*Hh + c];
        g_Gt[gid] = s * scale;
    }
    if (gid < Hh) {
        float s = 0.f, t = 0.f;
        #pragma unroll 8
        for (int o = 0; o < Hh; o++) { s += Wq[o*Hh + gid] * bk[o]; t += Wk[o*Hh + gid] * bq[o]; }
        g_u[gid] = s * scale;
        g_w[gid] = t * scale;
    }
    if (gid == 0) {
        float s = 0.f;
        for (int o = 0; o < Hh; o++) s += bq[o] * bk[o];
        g_c0 = s * scale;
    }
}

__device__ __forceinline__ void tf32x2(float x, uint32_t& h, uint32_t& l) {
    asm("cvt.rna.tf32.f32 %0, %1;" : "=r"(h) : "f"(x));
    float r = x - __uint_as_float(h);
    asm("cvt.rna.tf32.f32 %0, %1;" : "=r"(l) : "f"(r));
}

__global__ void precompute_pack(const float* __restrict__ Wv) {
    int gid = blockIdx.x * blockDim.x + threadIdx.x;
    if (gid >= 9216) return;
    int mat = gid / 4608;            // 0: G (unpermuted), 1: Wv (k-permuted)
    int rem = gid % 4608;
    int r = rem / WS, p = rem % WS;
    float v = 0.f;
    if (p < 64) {
        int c = mat ? kperm_inv(p) : p;
        v = mat ? Wv[r*64 + c] : g_Gt[r*64 + c];
    }
    uint32_t h, l;
    tf32x2(v, h, l);
    g_wsplit[mat*9216 + rem]        = __uint_as_float(h);
    g_wsplit[mat*9216 + 4608 + rem] = __uint_as_float(l);
}

// ---------------- mma helpers ----------------
__device__ __forceinline__ void mma8(float c[4], uint32_t a0, uint32_t a1, uint32_t a2, uint32_t a3,
                                     uint32_t b0, uint32_t b1) {
    asm volatile(
        "mma.sync.aligned.m16n8k8.row.col.f32.tf32.tf32.f32 "
        "{%0,%1,%2,%3}, {%4,%5,%6,%7}, {%8,%9}, {%0,%1,%2,%3};"
        : "+f"(c[0]), "+f"(c[1]), "+f"(c[2]), "+f"(c[3])
        : "r"(a0), "r"(a1), "r"(a2), "r"(a3), "r"(b0), "r"(b1));
}

// A fp32 stride 68 (split on the fly), B pre-split stride 72 UNPERMUTED (scalar loads)
__device__ __forceinline__ void gemm_flyP(const float* __restrict__ A,
                                          const float* __restrict__ Bh, const float* __restrict__ Bl,
                                          int mb, int n0, int lane, float acc[4][4]) {
    const int g = lane >> 2, q = lane & 3;
    const float* ar0 = A + (mb + g) * XS + q;
    const float* ar1 = A + (mb + g + 8) * XS + q;
    #pragma unroll
    for (int k0 = 0; k0 < 64; k0 += 8) {
        uint32_t ah[4], al[4];
        tf32x2(ar0[k0],   ah[0], al[0]);
        tf32x2(ar1[k0],   ah[1], al[1]);
        tf32x2(ar0[k0+4], ah[2], al[2]);
        tf32x2(ar1[k0+4], ah[3], al[3]);
        #pragma unroll
        for (int nt = 0; nt < 4; nt++) {
            int bi = (n0 + 8*nt + g) * WS + k0 + q;
            uint32_t b0h = __float_as_uint(Bh[bi]), b1h = __float_as_uint(Bh[bi+4]);
            uint32_t b0l = __float_as_uint(Bl[bi]), b1l = __float_as_uint(Bl[bi+4]);
            mma8(acc[nt], ah[0],ah[1],ah[2],ah[3], b0h, b1h);
            mma8(acc[nt], ah[0],ah[1],ah[2],ah[3], b0l, b1l);
            mma8(acc[nt], al[0],al[1],al[2],al[3], b0h, b1h);
        }
    }
}

// A and B pre-split, stride 72, k-pair-permuted: all fragments via float2 (LDS.64)
__device__ __forceinline__ void gemm_pair(const float* __restrict__ Ah, const float* __restrict__ Al,
                                          const float* __restrict__ Bh, const float* __restrict__ Bl,
                                          int mb, int n0, int lane, float acc[4][4]) {
    const int g = lane >> 2, q = lane & 3;
    const float* a0h = Ah + (mb + g) * WS + 2*q;
    const float* a1h = Ah + (mb + g + 8) * WS + 2*q;
    const float* a0l = Al + (mb + g) * WS + 2*q;
    const float* a1l = Al + (mb + g + 8) * WS + 2*q;
    #pragma unroll
    for (int k0 = 0; k0 < 64; k0 += 8) {
        float2 xh0 = *(const float2*)(a0h + k0);
        float2 xh1 = *(const float2*)(a1h + k0);
        float2 xl0 = *(const float2*)(a0l + k0);
        float2 xl1 = *(const float2*)(a1l + k0);
        uint32_t ah0 = __float_as_uint(xh0.x), ah1 = __float_as_uint(xh1.x);
        uint32_t ah2 = __float_as_uint(xh0.y), ah3 = __float_as_uint(xh1.y);
        uint32_t al0 = __float_as_uint(xl0.x), al1 = __float_as_uint(xl1.x);
        uint32_t al2 = __float_as_uint(xl0.y), al3 = __float_as_uint(xl1.y);
        #pragma unroll
        for (int nt = 0; nt < 4; nt++) {
            const float* bp = Bh + (n0 + 8*nt + g) * WS + k0 + 2*q;
            const float* bq_ = Bl + (n0 + 8*nt + g) * WS + k0 + 2*q;
            float2 bh = *(const float2*)bp;
            float2 bl = *(const float2*)bq_;
            uint32_t b0h = __float_as_uint(bh.x), b1h = __float_as_uint(bh.y);
            uint32_t b0l = __float_as_uint(bl.x), b1l = __float_as_uint(bl.y);
            mma8(acc[nt], ah0,ah1,ah2,ah3, b0h, b1h);
            mma8(acc[nt], ah0,ah1,ah2,ah3, b0l, b1l);
            mma8(acc[nt], al0,al1,al2,al3, b0h, b1h);
        }
    }
}

__device__ __forceinline__ unsigned f2mono(float v) {
    unsigned u = __float_as_uint(v);
    return (u & 0x80000000u) ? ~u : (u | 0x80000000u);
}
__device__ __forceinline__ float mono2f(unsigned k) {
    unsigned u = (k & 0x80000000u) ? (k ^ 0x80000000u) : ~k;
    return __uint_as_float(u);
}

extern __shared__ float smf[];
__global__ void __launch_bounds__(NTH, 1)
fused_align_k(const float* __restrict__ traffic, const float* __restrict__ text,
              const float* __restrict__ Wv, const float* __restrict__ bv,
              const float* __restrict__ gamma, const float* __restrict__ beta,
              const int* __restrict__ topk_p,
              float* __restrict__ out_main, float* __restrict__ out_attn) {
    float* xt_tr = smf + F_XTR;
    float* xtxh  = smf + F_XTXH;
    float* xtxl  = smf + F_XTXL;
    float* Wr    = smf + F_W;       // Gh|Gl|Wvh|Wvl -> PH|PL
    float* vsm   = smf + F_VSM;
    float* sc    = smf + F_SC;
    float* avl   = smf + F_AVL;
    float* rb  = smf + F_TAIL;
    float* cb  = rb + 128;
    float* sg  = cb + 128;
    float* sb  = sg + 64;
    float* sbv = sb + 64;

    const int tid = threadIdx.x;
    const int lane = tid & 31;
    const int wrp = tid >> 5;
    const int m = blockIdx.x;
    const int b = m >> 9;
    const int n = m & (Nn - 1);

    const float* tr_base = traffic + ((size_t)b * Ss * Nn + n) * Hh;
    const float* tx_base = text    + ((size_t)b * Ss * Nn + n) * Hh;

    // ---- Stage 0: weights copy, tiles, biases ----
    for (int i = tid; i < 4608; i += NTH)
        ((uint4*)Wr)[i] = ((const uint4*)g_wsplit)[i];
    #pragma unroll
    for (int it = 0; it < 2; it++) {
        int i = tid + it * NTH;
        int r = i >> 4, f = i & 15;
        float4 a  = *(const float4*)(tr_base + (size_t)r * Nn * Hh + f * 4);
        float4 bx = *(const float4*)(tx_base + (size_t)r * Nn * Hh + f * 4);
        *(float4*)(xt_tr + r * XS + f * 4) = a;
        // split Xtx -> tf32 hi/lo at k-pair-permuted positions
        uint32_t h0,l0,h1,l1,h2,l2,h3,l3;
        tf32x2(bx.x,h0,l0); tf32x2(bx.y,h1,l1); tf32x2(bx.z,h2,l2); tf32x2(bx.w,h3,l3);
        int pbase = r * WS + ((f >> 1) << 3) + (f & 1);   // + (j<<1) per element
        xtxh[pbase + 0] = __uint_as_float(h0);  xtxl[pbase + 0] = __uint_as_float(l0);
        xtxh[pbase + 2] = __uint_as_float(h1);  xtxl[pbase + 2] = __uint_as_float(l1);
        xtxh[pbase + 4] = __uint_as_float(h2);  xtxl[pbase + 4] = __uint_as_float(l2);
        xtxh[pbase + 6] = __uint_as_float(h3);  xtxl[pbase + 6] = __uint_as_float(l3);
        // fused bias partials
        float4 uu = *(const float4*)(g_u + f * 4);
        float4 ww = *(const float4*)(g_w + f * 4);
        float pr = a.x*uu.x + a.y*uu.y + a.z*uu.z + a.w*uu.w;
        float pc = bx.x*ww.x + bx.y*ww.y + bx.z*ww.z + bx.w*ww.w;
        #pragma unroll
        for (int o = 8; o > 0; o >>= 1) {
            pr += __shfl_xor_sync(0xffffffffu, pr, o);
            pc += __shfl_xor_sync(0xffffffffu, pc, o);
        }
        if (f == 0) { rb[r] = pr + g_c0; cb[r] = pc; }
    }
    if (tid < 64) { sg[tid] = gamma[tid]; sb[tid] = beta[tid]; sbv[tid] = bv[tid]; }
    __syncthreads();

    const int g = lane >> 2, q = lane & 3;

    // ---- Phase 1: P (warps 0-15) / V (warps 16-31) ----
    float accPV[4][4];
    #pragma unroll
    for (int i = 0; i < 4; i++)
        #pragma unroll
        for (int j = 0; j < 4; j++) accPV[i][j] = 0.f;
    int w2 = (wrp < 16) ? wrp : (wrp - 16);
    const int mb = (w2 >> 1) * 16, n0 = (w2 & 1) * 32;
    if (wrp < 16) {
        gemm_flyP(xt_tr, Wr, Wr + 4608, mb, n0, lane, accPV);          // P = Xtr @ G^T
    } else {
        gemm_pair(xtxh, xtxl, Wr + 9216, Wr + 13824, mb, n0, lane, accPV);  // V
        #pragma unroll
        for (int nt = 0; nt < 4; nt++) {
            int col = n0 + 8*nt + 2*q;
            *(float2*)(vsm + (mb + g) * XS + col)     = make_float2(accPV[nt][0] + sbv[col], accPV[nt][1] + sbv[col+1]);
            *(float2*)(vsm + (mb + g + 8) * XS + col) = make_float2(accPV[nt][2] + sbv[col], accPV[nt][3] + sbv[col+1]);
        }
    }
    __syncthreads();          // all G/Wv reads done
    if (wrp < 16) {           // split P -> PH/PL (overlay W), k-pair-permuted cols
        float* PH = Wr;
        float* PL = Wr + 9216;
        #pragma unroll
        for (int nt = 0; nt < 4; nt++) {
            int c0 = n0 + 8*nt + 2*q, c1 = c0 + 1;
            int p0 = kperm(c0), p1 = kperm(c1);
            int rA = (mb + g) * WS, rB = (mb + g + 8) * WS;
            uint32_t h, l;
            tf32x2(accPV[nt][0], h, l); PH[rA + p0] = __uint_as_float(h); PL[rA + p0] = __uint_as_float(l);
            tf32x2(accPV[nt][1], h, l); PH[rA + p1] = __uint_as_float(h); PL[rA + p1] = __uint_as_float(l);
            tf32x2(accPV[nt][2], h, l); PH[rB + p0] = __uint_as_float(h); PL[rB + p0] = __uint_as_float(l);
            tf32x2(accPV[nt][3], h, l); PH[rB + p1] = __uint_as_float(h); PL[rB + p1] = __uint_as_float(l);
        }
    }
    __syncthreads();          // PH/PL visible

    // ---- Phase 2: S = P @ Xtx^T (all 32 warps, m16 x n32 tiles) ----
    float accS[4][4];
    #pragma unroll
    for (int i = 0; i < 4; i++)
        #pragma unroll
        for (int j = 0; j < 4; j++) accS[i][j] = 0.f;
    const int smbm = (wrp >> 2) * 16, sn0 = (wrp & 3) * 32;
    gemm_pair(Wr, Wr + 9216, xtxh, xtxl, smbm, sn0, lane, accS);
    __syncthreads();          // all P/Xtx reads done -> safe to overlay scores
    #pragma unroll
    for (int nt = 0; nt < 4; nt++) {
        int col = sn0 + 8*nt + 2*q;
        *(float2*)(sc + (smbm + g) * SS + col)     = make_float2(accS[nt][0], accS[nt][1]);
        *(float2*)(sc + (smbm + g + 8) * SS + col) = make_float2(accS[nt][2], accS[nt][3]);
    }
    __syncthreads();

    // ---- Stage 3: per-row top-k + softmax + attn + sparse AV + LN ----
    int kk = 16;
    if (topk_p) { kk = topk_p[0]; if (kk < 1) kk = 1; if (kk > 32) kk = 32; }

    const int r0 = wrp * 4;
    float* attn_base = out_attn + (size_t)m * Ss * Ss;
    const unsigned FULL = 0xffffffffu;

    for (int ri = 0; ri < 4; ++ri) {
        const int s = r0 + ri;
        const float rbias = rb[s];
        float o0 = sc[s * SS + lane]      + rbias + cb[lane];
        float o1 = sc[s * SS + lane + 32] + rbias + cb[lane + 32];
        float o2 = sc[s * SS + lane + 64] + rbias + cb[lane + 64];
        float o3 = sc[s * SS + lane + 96] + rbias + cb[lane + 96];
        unsigned k0 = f2mono(o0), k1 = f2mono(o1), k2 = f2mono(o2), k3 = f2mono(o3);
        unsigned l0 = k0, l1 = k1, l2 = k2, l3 = k3;
        unsigned maxk = 0, thrk = 0, selk = 0; int seli = 0;

        for (int it = 0; it < kk; ++it) {
            unsigned lb = l0; int slot = 0;
            if (l1 > lb) { lb = l1; slot = 1; }
            if (l2 > lb) { lb = l2; slot = 2; }
            if (l3 > lb) { lb = l3; slot = 3; }
            unsigned mw = __reduce_max_sync(FULL, lb);
            unsigned cand = (lb == mw) ? (unsigned)(slot * 32 + lane) : 0xffffffffu;
            unsigned tsel = __reduce_min_sync(FULL, cand);
            if (it == 0) maxk = mw;
            thrk = mw;
            if (lane == (int)(tsel & 31)) {
                int js = tsel >> 5;
                if (js == 0) l0 = 0; else if (js == 1) l1 = 0;
                else if (js == 2) l2 = 0; else l3 = 0;
            }
            if (lane == it) { selk = mw; seli = (int)tsel; }
        }

        float maxv = mono2f(maxk);
        float e0 = (k0 >= thrk) ? __expf(o0 - maxv) : 0.f;
        float e1 = (k1 >= thrk) ? __expf(o1 - maxv) : 0.f;
        float e2 = (k2 >= thrk) ? __expf(o2 - maxv) : 0.f;
        float e3 = (k3 >= thrk) ? __expf(o3 - maxv) : 0.f;
        float z = e0 + e1 + e2 + e3;
        #pragma unroll
        for (int off = 16; off > 0; off >>= 1) z += __shfl_xor_sync(FULL, z, off);
        float inv = 1.0f / z;

        float* ab = attn_base + (size_t)s * Ss;
        ab[lane]      = e0 * inv;
        ab[lane + 32] = e1 * inv;
        ab[lane + 64] = e2 * inv;
        ab[lane + 96] = e3 * inv;

        // publish (p, idx) list to smem, then broadcast-read (replaces shfl pairs)
        if (lane < kk) {
            float p = __expf(mono2f(selk) - maxv) * inv;
            *(float2*)(avl + (s * 32 + lane) * 2) = make_float2(p, __int_as_float(seli));
        }
        __syncwarp();
        float a0 = 0.f, a1 = 0.f;
        for (int i2 = 0; i2 < kk; i2++) {
            float2 pv = *(const float2*)(avl + (s * 32 + i2) * 2);   // broadcast
            int ti = __float_as_int(pv.y);
            const float* vr = vsm + ti * XS;
            a0 += pv.x * vr[lane];
            a1 += pv.x * vr[lane + 32];
        }

        float rr0 = a0 + xt_tr[s * XS + lane];
        float rr1 = a1 + xt_tr[s * XS + lane + 32];
        float sm1 = rr0 + rr1;
        #pragma unroll
        for (int off = 16; off > 0; off >>= 1) sm1 += __shfl_xor_sync(FULL, sm1, off);
        float mu = sm1 * (1.0f / 64.0f);
        float d0 = rr0 - mu, d1 = rr1 - mu;
        float sq = d0 * d0 + d1 * d1;
        #pragma unroll
        for (int off = 16; off > 0; off >>= 1) sq += __shfl_xor_sync(FULL, sq, off);
        float inv_sd = rsqrtf(sq * (1.0f / 64.0f) + 1e-5f);

        float* ob = out_main + (((size_t)(b * Ss + s)) * Nn + n) * Hh;
        ob[lane]      = d0 * inv_sd * sg[lane]      + sb[lane];
        ob[lane + 32] = d1 * inv_sd * sg[lane + 32] + sb[lane + 32];
    }
}

extern "C" void kernel_launch(void* const* d_in, const int* in_sizes, int n_in,
                              void* d_out, int out_size) {
    const float* traffic = (const float*)d_in[0];
    const float* text    = (const float*)d_in[1];
    const float* Wq      = (const float*)d_in[2];
    const float* bq      = (const float*)d_in[3];
    const float* Wk      = (const float*)d_in[4];
    const float* bk      = (const float*)d_in[5];
    const float* Wv      = (const float*)d_in[6];
    const float* bv      = (const float*)d_in[7];
    const float* gamma   = (const float*)d_in[8];
    const float* beta    = (const float*)d_in[9];
    const int*   topk    = (n_in > 10) ? (const int*)d_in[10] : nullptr;

    float* out  = (float*)d_out;
    float* attn = out + (size_t)Bb * Ss * Nn * Hh;

    size_t smem = (size_t)SMEM_FLOATS * sizeof(float);   // ~214 KB
    cudaFuncSetAttribute(fused_align_k, cudaFuncAttributeMaxDynamicSharedMemorySize, (int)smem);

    precompute_k<<<16, 256>>>(Wq, bq, Wk, bk);
    precompute_pack<<<36, 256>>>(Wv);
    fused_align_k<<<Mm, NTH, smem>>>(traffic, text, Wv, bv, gamma, beta, topk, out, attn);
}

// round 10
// speedup vs baseline: 1.2838x; 1.0043x over previous
#include <cuda_runtime.h>
#include <stdint.h>
#include <math.h>

#define Bb 4
#define Ss 128
#define Nn 512
#define Hh 64
#define Mm 2048
#define XS 68        // fp32 tile stride (conflict-free: banks 4g+q)
#define SSTR 132     // scores stride
#define NTH 512

// smem float offsets (regions with chained lifetimes)
#define F_R1   0       // Xtr [128][68] -> P -> scores[0:8704)
#define F_R2   8704    // Xtx [128][68] -> scores[8704:17408)
#define F_R3   17408   // G[64][68] | Wv[64][68] -> V [128][68]
#define F_TAIL 26112   // rb128 cb128 sg64 sb64 sbv64
#define SMEM_FLOATS 26560   // 106240 bytes

// ---------------- precomputed operands ----------------
__device__ float g_Gt[Hh*Hh];   // [c][h] = scale * sum_o Wq[o][h] Wk[o][c]
__device__ float g_u[Hh];
__device__ float g_w[Hh];
__device__ float g_c0;

__global__ void precompute_k(const float* __restrict__ Wq, const float* __restrict__ bq,
                             const float* __restrict__ Wk, const float* __restrict__ bk) {
    int gid = blockIdx.x * blockDim.x + threadIdx.x;
    const float scale = 0.125f;
    if (gid < Hh * Hh) {
        int c = gid >> 6, h = gid & 63;
        float s = 0.f;
        #pragma unroll 8
        for (int o = 0; o < Hh; o++) s += Wq[o*Hh + h] * Wk[o*Hh + c];
        g_Gt[gid] = s * scale;
    }
    if (gid < Hh) {
        float s = 0.f, t = 0.f;
        #pragma unroll 8
        for (int o = 0; o < Hh; o++) { s += Wq[o*Hh + gid] * bk[o]; t += Wk[o*Hh + gid] * bq[o]; }
        g_u[gid] = s * scale;
        g_w[gid] = t * scale;
    }
    if (gid == 0) {
        float s = 0.f;
        for (int o = 0; o < Hh; o++) s += bq[o] * bk[o];
        g_c0 = s * scale;
    }
}

// ---------------- device helpers ----------------
__device__ __forceinline__ void tf32x2(float x, uint32_t& h, uint32_t& l) {
    asm("cvt.rna.tf32.f32 %0, %1;" : "=r"(h) : "f"(x));
    float r = x - __uint_as_float(h);
    asm("cvt.rna.tf32.f32 %0, %1;" : "=r"(l) : "f"(r));
}
__device__ __forceinline__ void mma8(float c[4], uint32_t a0, uint32_t a1, uint32_t a2, uint32_t a3,
                                     uint32_t b0, uint32_t b1) {
    asm volatile(
        "mma.sync.aligned.m16n8k8.row.col.f32.tf32.tf32.f32 "
        "{%0,%1,%2,%3}, {%4,%5,%6,%7}, {%8,%9}, {%0,%1,%2,%3};"
        : "+f"(c[0]), "+f"(c[1]), "+f"(c[2]), "+f"(c[3])
        : "r"(a0), "r"(a1), "r"(a2), "r"(a3), "r"(b0), "r"(b1));
}
__device__ __forceinline__ unsigned f2mono(float v) {
    unsigned u = __float_as_uint(v);
    return (u & 0x80000000u) ? ~u : (u | 0x80000000u);
}
__device__ __forceinline__ float mono2f(unsigned k) {
    unsigned u = (k & 0x80000000u) ? (k ^ 0x80000000u) : ~k;
    return __uint_as_float(u);
}

// GEMM: A,B fp32 in smem (stride 68), both tf32-split on the fly.
// Warp tile m16 x (8*NT), 3-product scheme. NT n-subtiles of 8.
template<int NT>
__device__ __forceinline__ void gemm_fly(const float* __restrict__ A, const float* __restrict__ B,
                                         int mb, int n0, int lane, float acc[NT][4]) {
    const int g = lane >> 2, q = lane & 3;
    const float* ar0 = A + (mb + g) * XS + q;
    const float* ar1 = A + (mb + g + 8) * XS + q;
    #pragma unroll
    for (int k0 = 0; k0 < 64; k0 += 8) {
        uint32_t ah[4], al[4];
        tf32x2(ar0[k0],   ah[0], al[0]);
        tf32x2(ar1[k0],   ah[1], al[1]);
        tf32x2(ar0[k0+4], ah[2], al[2]);
        tf32x2(ar1[k0+4], ah[3], al[3]);
        #pragma unroll
        for (int nt = 0; nt < NT; nt++) {
            const float* bp = B + (n0 + 8*nt + g) * XS + k0 + q;
            uint32_t b0h, b0l, b1h, b1l;
            tf32x2(bp[0], b0h, b0l);
            tf32x2(bp[4], b1h, b1l);
            mma8(acc[nt], ah[0],ah[1],ah[2],ah[3], b0h, b1h);
            mma8(acc[nt], ah[0],ah[1],ah[2],ah[3], b0l, b1l);
            mma8(acc[nt], al[0],al[1],al[2],al[3], b0h, b1h);
        }
    }
}

extern __shared__ float smf[];
__global__ void __launch_bounds__(NTH, 2)
fused_align_k(const float* __restrict__ traffic, const float* __restrict__ text,
              const float* __restrict__ Wv, const float* __restrict__ bv,
              const float* __restrict__ gamma, const float* __restrict__ beta,
              const int* __restrict__ topk_p,
              float* __restrict__ out_main, float* __restrict__ out_attn) {
    float* R1  = smf + F_R1;     // Xtr -> P -> scores lo
    float* R2  = smf + F_R2;     // Xtx -> scores hi
    float* R3  = smf + F_R3;     // G|Wv -> V
    float* sc  = smf + F_R1;     // scores [128][132] over R1+R2
    float* rb  = smf + F_TAIL;
    float* cb  = rb + 128;
    float* sg  = cb + 128;
    float* sb  = sg + 64;
    float* sbv = sb + 64;

    const int tid = threadIdx.x;
    const int lane = tid & 31;
    const int wrp = tid >> 5;       // 0..15
    const int m = blockIdx.x;
    const int b = m >> 9;
    const int n = m & (Nn - 1);

    const float* tr_base = traffic + ((size_t)b * Ss * Nn + n) * Hh;
    const float* tx_base = text    + ((size_t)b * Ss * Nn + n) * Hh;

    // ---- Stage 0: weights (fp32) + X tiles + fused biases ----
    for (int i = tid; i < 4096; i += NTH) R3[(i >> 6) * XS + (i & 63)]        = g_Gt[i];
    for (int i = tid; i < 4096; i += NTH) R3[4352 + (i >> 6) * XS + (i & 63)] = Wv[i];
    #pragma unroll
    for (int it = 0; it < 4; it++) {
        int i = tid + it * NTH;          // 0..2047
        int r = i >> 4, f = i & 15;
        float4 a  = *(const float4*)(tr_base + (size_t)r * Nn * Hh + f * 4);
        float4 bx = *(const float4*)(tx_base + (size_t)r * Nn * Hh + f * 4);
        *(float4*)(R1 + r * XS + f * 4) = a;
        *(float4*)(R2 + r * XS + f * 4) = bx;
        float4 uu = *(const float4*)(g_u + f * 4);
        float4 ww = *(const float4*)(g_w + f * 4);
        float pr = a.x*uu.x + a.y*uu.y + a.z*uu.z + a.w*uu.w;
        float pc = bx.x*ww.x + bx.y*ww.y + bx.z*ww.z + bx.w*ww.w;
        #pragma unroll
        for (int o = 8; o > 0; o >>= 1) {
            pr += __shfl_xor_sync(0xffffffffu, pr, o);
            pc += __shfl_xor_sync(0xffffffffu, pc, o);
        }
        if (f == 0) { rb[r] = pr + g_c0; cb[r] = pc; }
    }
    if (tid < 64) { sg[tid] = gamma[tid]; sb[tid] = beta[tid]; sbv[tid] = bv[tid]; }
    __syncthreads();

    const int g = lane >> 2, q = lane & 3;

    // ---- Phase 1: P = Xtr @ G^T (16 warps: 8 m-tiles x 2 n-tiles) ----
    {
        float acc[4][4];
        #pragma unroll
        for (int i = 0; i < 4; i++)
            #pragma unroll
            for (int j = 0; j < 4; j++) acc[i][j] = 0.f;
        const int mb = (wrp >> 1) * 16, n0 = (wrp & 1) * 32;
        gemm_fly<4>(R1, R3, mb, n0, lane, acc);
        __syncthreads();                 // Xtr & G reads done
        #pragma unroll
        for (int nt = 0; nt < 4; nt++) { // P over Xtr (R1)
            int col = n0 + 8*nt + 2*q;
            *(float2*)(R1 + (mb + g) * XS + col)     = make_float2(acc[nt][0], acc[nt][1]);
            *(float2*)(R1 + (mb + g + 8) * XS + col) = make_float2(acc[nt][2], acc[nt][3]);
        }
    }
    __syncthreads();                     // P visible

    // ---- Phase 2: V = Xtx @ Wv^T ----
    {
        float acc[4][4];
        #pragma unroll
        for (int i = 0; i < 4; i++)
            #pragma unroll
            for (int j = 0; j < 4; j++) acc[i][j] = 0.f;
        const int mb = (wrp >> 1) * 16, n0 = (wrp & 1) * 32;
        gemm_fly<4>(R2, R3 + 4352, mb, n0, lane, acc);
        __syncthreads();                 // Wv reads done
        #pragma unroll
        for (int nt = 0; nt < 4; nt++) { // V over G|Wv (R3)
            int col = n0 + 8*nt + 2*q;
            *(float2*)(R3 + (mb + g) * XS + col)     = make_float2(acc[nt][0] + sbv[col], acc[nt][1] + sbv[col+1]);
            *(float2*)(R3 + (mb + g + 8) * XS + col) = make_float2(acc[nt][2] + sbv[col], acc[nt][3] + sbv[col+1]);
        }
    }
    __syncthreads();                     // V visible

    // ---- Phase 3: S = P @ Xtx^T (16 warps: 8 m-tiles x 2 n64-tiles) ----
    {
        float acc[8][4];
        #pragma unroll
        for (int i = 0; i < 8; i++)
            #pragma unroll
            for (int j = 0; j < 4; j++) acc[i][j] = 0.f;
        const int mb = (wrp >> 1) * 16, n0 = (wrp & 1) * 64;
        gemm_fly<8>(R1, R2, mb, n0, lane, acc);
        __syncthreads();                 // P & Xtx reads done -> overlay scores
        #pragma unroll
        for (int nt = 0; nt < 8; nt++) {
            int col = n0 + 8*nt + 2*q;
            *(float2*)(sc + (mb + g) * SSTR + col)     = make_float2(acc[nt][0], acc[nt][1]);
            *(float2*)(sc + (mb + g + 8) * SSTR + col) = make_float2(acc[nt][2], acc[nt][3]);
        }
    }
    __syncthreads();

    // ---- Stage 3: per-row top-k + softmax + attn + sparse AV + LN (8 rows/warp) ----
    int kk = 16;
    if (topk_p) { kk = topk_p[0]; if (kk < 1) kk = 1; if (kk > 32) kk = 32; }

    const int r0 = wrp * 8;
    float* attn_base = out_attn + (size_t)m * Ss * Ss;
    const unsigned FULL = 0xffffffffu;

    // prefetch residual from global (MLP=16)
    float resA[8], resB[8];
    #pragma unroll
    for (int ri = 0; ri < 8; ri++) {
        resA[ri] = tr_base[(size_t)(r0 + ri) * Nn * Hh + lane];
        resB[ri] = tr_base[(size_t)(r0 + ri) * Nn * Hh + lane + 32];
    }

    for (int ri = 0; ri < 8; ++ri) {
        const int s = r0 + ri;
        const float rbias = rb[s];
        float o0 = sc[s * SSTR + lane]      + rbias + cb[lane];
        float o1 = sc[s * SSTR + lane + 32] + rbias + cb[lane + 32];
        float o2 = sc[s * SSTR + lane + 64] + rbias + cb[lane + 64];
        float o3 = sc[s * SSTR + lane + 96] + rbias + cb[lane + 96];
        unsigned k0 = f2mono(o0), k1 = f2mono(o1), k2 = f2mono(o2), k3 = f2mono(o3);
        unsigned l0 = k0, l1 = k1, l2 = k2, l3 = k3;
        unsigned maxk = 0, thrk = 0, selk = 0; int seli = 0;

        for (int it = 0; it < kk; ++it) {
            unsigned lb = l0; int slot = 0;
            if (l1 > lb) { lb = l1; slot = 1; }
            if (l2 > lb) { lb = l2; slot = 2; }
            if (l3 > lb) { lb = l3; slot = 3; }
            unsigned mw = __reduce_max_sync(FULL, lb);
            unsigned cand = (lb == mw) ? (unsigned)(slot * 32 + lane) : 0xffffffffu;
            unsigned tsel = __reduce_min_sync(FULL, cand);
            if (it == 0) maxk = mw;
            thrk = mw;
            if (lane == (int)(tsel & 31)) {
                int js = tsel >> 5;
                if (js == 0) l0 = 0; else if (js == 1) l1 = 0;
                else if (js == 2) l2 = 0; else l3 = 0;
            }
            if (lane == it) { selk = mw; seli = (int)tsel; }
        }

        float maxv = mono2f(maxk);
        float e0 = (k0 >= thrk) ? __expf(o0 - maxv) : 0.f;
        float e1 = (k1 >= thrk) ? __expf(o1 - maxv) : 0.f;
        float e2 = (k2 >= thrk) ? __expf(o2 - maxv) : 0.f;
        float e3 = (k3 >= thrk) ? __expf(o3 - maxv) : 0.f;
        float z = e0 + e1 + e2 + e3;
        #pragma unroll
        for (int off = 16; off > 0; off >>= 1) z += __shfl_xor_sync(FULL, z, off);
        float inv = 1.0f / z;

        float* ab = attn_base + (size_t)s * Ss;
        ab[lane]      = e0 * inv;
        ab[lane + 32] = e1 * inv;
        ab[lane + 64] = e2 * inv;
        ab[lane + 96] = e3 * inv;

        float p = (lane < kk) ? __expf(mono2f(selk) - maxv) * inv : 0.f;
        float a0 = 0.f, a1 = 0.f;
        for (int i2 = 0; i2 < kk; i2++) {
            float pi = __shfl_sync(FULL, p, i2);
            int   ti = __shfl_sync(FULL, seli, i2);
            const float* vr = R3 + ti * XS;
            a0 += pi * vr[lane];
            a1 += pi * vr[lane + 32];
        }

        float rr0 = a0 + resA[ri];
        float rr1 = a1 + resB[ri];
        float sm1 = rr0 + rr1;
        #pragma unroll
        for (int off = 16; off > 0; off >>= 1) sm1 += __shfl_xor_sync(FULL, sm1, off);
        float mu = sm1 * (1.0f / 64.0f);
        float d0 = rr0 - mu, d1 = rr1 - mu;
        float sq = d0 * d0 + d1 * d1;
        #pragma unroll
        for (int off = 16; off > 0; off >>= 1) sq += __shfl_xor_sync(FULL, sq, off);
        float inv_sd = rsqrtf(sq * (1.0f / 64.0f) + 1e-5f);

        float* ob = out_main + (((size_t)(b * Ss + s)) * Nn + n) * Hh;
        ob[lane]      = d0 * inv_sd * sg[lane]      + sb[lane];
        ob[lane + 32] = d1 * inv_sd * sg[lane + 32] + sb[lane + 32];
    }
}

extern "C" void kernel_launch(void* const* d_in, const int* in_sizes, int n_in,
                              void* d_out, int out_size) {
    const float* traffic = (const float*)d_in[0];
    const float* text    = (const float*)d_in[1];
    const float* Wq      = (const float*)d_in[2];
    const float* bq      = (const float*)d_in[3];
    const float* Wk      = (const float*)d_in[4];
    const float* bk      = (const float*)d_in[5];
    const float* Wv      = (const float*)d_in[6];
    const float* bv      = (const float*)d_in[7];
    const float* gamma   = (const float*)d_in[8];
    const float* beta    = (const float*)d_in[9];
    const int*   topk    = (n_in > 10) ? (const int*)d_in[10] : nullptr;

    float* out  = (float*)d_out;
    float* attn = out + (size_t)Bb * Ss * Nn * Hh;

    size_t smem = (size_t)SMEM_FLOATS * sizeof(float);   // 106240 B -> 2 CTAs/SM
    cudaFuncSetAttribute(fused_align_k, cudaFuncAttributeMaxDynamicSharedMemorySize, (int)smem);

    precompute_k<<<16, 256>>>(Wq, bq, Wk, bk);
    fused_align_k<<<Mm, NTH, smem>>>(traffic, text, Wv, bv, gamma, beta, topk, out, attn);
}